// round 14
// baseline (speedup 1.0000x reference)
#include <cuda_runtime.h>
#include <cuda_fp16.h>
#include <stdint.h>

#define BH 64
#define KP 512
#define NN 4096
#define DD 64
#define XT 16384            // 128 x 64 fp16 tile, swizzled, 128B rows

// ---- hm_main smem layout (bytes): 2 x-arrays (xkhi, xvhi) x 2 buffers ----
#define M_X(b,c)  ((b) * 32768 + (c) * XT)
#define M_RZ  65536         // 2 x 512B raw z tiles
#define M_SMEM 66560

// ---- hm_z smem layout: xhi + K hi/lo double-buffered ----
#define Z_XHI 0
#define Z_K(b,c) (16384 + (b) * 32768 + (c) * XT)
#define Z_ZP 81920
#define Z_SMEM 82944

__device__ float g_z[BH * NN];
__device__ __align__(16) __half g_K_hi[BH * KP * DD];
__device__ __align__(16) __half g_K_lo[BH * KP * DD];
__device__ __align__(16) __half g_xk_hi[BH * NN * DD];
__device__ __align__(16) __half g_xv_hi[BH * NN * DD];

// ---------------------------------------------------------------- helpers
__device__ __forceinline__ uint32_t s2u(const void* p) {
    return (uint32_t)__cvta_generic_to_shared(p);
}
__device__ __forceinline__ void mma_f16(float* c, const uint32_t* a, const uint32_t* b) {
    asm volatile(
        "mma.sync.aligned.m16n8k16.row.col.f32.f16.f16.f32 "
        "{%0,%1,%2,%3}, {%4,%5,%6,%7}, {%8,%9}, {%0,%1,%2,%3};"
        : "+f"(c[0]), "+f"(c[1]), "+f"(c[2]), "+f"(c[3])
        : "r"(a[0]), "r"(a[1]), "r"(a[2]), "r"(a[3]), "r"(b[0]), "r"(b[1]));
}
__device__ __forceinline__ void ldsm4(uint32_t* r, uint32_t addr) {
    asm volatile("ldmatrix.sync.aligned.m8n8.x4.shared.b16 {%0,%1,%2,%3}, [%4];"
        : "=r"(r[0]), "=r"(r[1]), "=r"(r[2]), "=r"(r[3]) : "r"(addr));
}
__device__ __forceinline__ void ldsm4t(uint32_t* r, uint32_t addr) {
    asm volatile("ldmatrix.sync.aligned.m8n8.x4.trans.shared.b16 {%0,%1,%2,%3}, [%4];"
        : "=r"(r[0]), "=r"(r[1]), "=r"(r[2]), "=r"(r[3]) : "r"(addr));
}
__device__ __forceinline__ void cpa(uint32_t dst, const void* src) {
    asm volatile("cp.async.cg.shared.global [%0], [%1], 16;" :: "r"(dst), "l"(src));
}
#define CPA_COMMIT() asm volatile("cp.async.commit_group;" ::: "memory")
__device__ __forceinline__ void cpa_wait1() { asm volatile("cp.async.wait_group 1;" ::: "memory"); }

// 128x64 fp16 tile (16KB) global -> swizzled smem (128B rows). 256 thr.
__device__ __forceinline__ void cpa_tile(uint32_t sbase, const __half* g, int tid) {
#pragma unroll
    for (int j = 0; j < 4; j++) {
        int ch = tid + j * 256;
        int row = ch >> 3, c = ch & 7;
        uint32_t off = (uint32_t)row * 128 + (((uint32_t)c * 16) ^ (((uint32_t)row & 7) << 4));
        cpa(sbase + off, (const char*)g + (size_t)ch * 16);
    }
}

// ---------------------------------------------------------------- split
// which: 0=K (hi+lo), 1=xk (hi only), 2=xv (hi only)
__global__ __launch_bounds__(256) void hm_split(const float4* __restrict__ Ksrc,
        const float4* __restrict__ xksrc, const float4* __restrict__ xvsrc) {
    int which = blockIdx.y;
    int n4 = (which == 0) ? (BH * KP * DD / 4) : (BH * NN * DD / 4);
    int i = blockIdx.x * 256 + threadIdx.x;
    if (i >= n4) return;
    const float4* src = (which == 0) ? Ksrc : (which == 1) ? xksrc : xvsrc;
    float4 v = src[i];
    __half2 h0 = __floats2half2_rn(v.x, v.y);
    __half2 h1 = __floats2half2_rn(v.z, v.w);
    uint2 hw;
    hw.x = *(uint32_t*)&h0; hw.y = *(uint32_t*)&h1;
    if (which == 1) { ((uint2*)g_xk_hi)[i] = hw; return; }
    if (which == 2) { ((uint2*)g_xv_hi)[i] = hw; return; }
    float2 f0 = __half22float2(h0), f1 = __half22float2(h1);
    __half2 l0 = __floats2half2_rn(v.x - f0.x, v.y - f0.y);
    __half2 l1 = __floats2half2_rn(v.z - f1.x, v.w - f1.y);
    uint2 lw;
    lw.x = *(uint32_t*)&l0; lw.y = *(uint32_t*)&l1;
    ((uint2*)g_K_hi)[i] = hw;
    ((uint2*)g_K_lo)[i] = lw;
}

// ---------------------------------------------------------------- pass 1: z
// dist = (Khi+Klo) @ xhi^T  (2-term, consistent with main pass)
__global__ __launch_bounds__(256) void hm_z() {
    extern __shared__ char sm[];
    const int tid = threadIdx.x, lane = tid & 31, wid = tid >> 5;
    const int kw = wid >> 2, nw = wid & 3;
    const int n0 = blockIdx.x * 128, bh = blockIdx.y;
    uint32_t sb = s2u(sm);

    cpa_tile(sb + Z_XHI, g_xk_hi + ((size_t)bh * NN + n0) * DD, tid);
    cpa_tile(sb + Z_K(0, 0), g_K_hi + (size_t)bh * KP * DD, tid);
    cpa_tile(sb + Z_K(0, 1), g_K_lo + (size_t)bh * KP * DD, tid);
    CPA_COMMIT();

    float zl[8];
#pragma unroll
    for (int i = 0; i < 8; i++) zl[i] = 0.f;

    const uint32_t sx = ((uint32_t)lane & 7) << 4;
    const uint32_t ar = (uint32_t)(kw * 64 + (lane & 15));
    const uint32_t br = (uint32_t)(nw * 32 + ((lane >> 4) & 1) * 8 + (lane & 7));

    for (int kt = 0; kt < 4; kt++) {
        if (kt + 1 < 4) {
            cpa_tile(sb + Z_K((kt + 1) & 1, 0), g_K_hi + ((size_t)bh * KP + (kt + 1) * 128) * DD, tid);
            cpa_tile(sb + Z_K((kt + 1) & 1, 1), g_K_lo + ((size_t)bh * KP + (kt + 1) * 128) * DD, tid);
        }
        CPA_COMMIT();
        cpa_wait1();
        __syncthreads();

        float C[4][4][4];
#pragma unroll
        for (int a = 0; a < 4; a++)
#pragma unroll
            for (int b = 0; b < 4; b++)
#pragma unroll
                for (int c = 0; c < 4; c++) C[a][b][c] = 0.f;
        {
            const uint32_t uKhi = sb + Z_K(kt & 1, 0), uKlo = sb + Z_K(kt & 1, 1);
            const uint32_t uXhi = sb + Z_XHI;
#pragma unroll
            for (int kc = 0; kc < 4; kc++) {
                const uint32_t acol = ((((uint32_t)lane >> 4) & 1) * 16 + kc * 32) ^ sx;
                const uint32_t bcol = ((((uint32_t)lane >> 3) & 1) * 16 + kc * 32) ^ sx;
                uint32_t ah[4][4], al[4][4], bh2[2][4];
#pragma unroll
                for (int mb = 0; mb < 4; mb++) {
                    ldsm4(ah[mb], uKhi + (ar + mb * 16) * 128 + acol);
                    ldsm4(al[mb], uKlo + (ar + mb * 16) * 128 + acol);
                }
#pragma unroll
                for (int g = 0; g < 2; g++)
                    ldsm4(bh2[g], uXhi + (br + g * 16) * 128 + bcol);
#pragma unroll
                for (int mb = 0; mb < 4; mb++)
#pragma unroll
                    for (int g = 0; g < 2; g++)
#pragma unroll
                        for (int nbb = 0; nbb < 2; nbb++)
                            mma_f16(C[mb][g * 2 + nbb], ah[mb], &bh2[g][nbb * 2]);
#pragma unroll
                for (int mb = 0; mb < 4; mb++)
#pragma unroll
                    for (int g = 0; g < 2; g++)
#pragma unroll
                        for (int nbb = 0; nbb < 2; nbb++)
                            mma_f16(C[mb][g * 2 + nbb], al[mb], &bh2[g][nbb * 2]);
            }
        }
#pragma unroll
        for (int mb = 0; mb < 4; mb++)
#pragma unroll
            for (int j = 0; j < 4; j++) {
                zl[2 * j]     += __expf(C[mb][j][0]) + __expf(C[mb][j][2]);
                zl[2 * j + 1] += __expf(C[mb][j][1]) + __expf(C[mb][j][3]);
            }
        __syncthreads();
    }
#pragma unroll
    for (int i = 0; i < 8; i++) {
        zl[i] += __shfl_xor_sync(~0u, zl[i], 4);
        zl[i] += __shfl_xor_sync(~0u, zl[i], 8);
        zl[i] += __shfl_xor_sync(~0u, zl[i], 16);
    }
    float* zp = (float*)(sm + Z_ZP);
    if (lane < 4) {
#pragma unroll
        for (int j = 0; j < 4; j++)
            *(float2*)&zp[kw * 128 + nw * 32 + j * 8 + lane * 2] =
                make_float2(zl[2 * j], zl[2 * j + 1]);
    }
    __syncthreads();
    if (tid < 128)
        g_z[(size_t)bh * NN + n0 + tid] = zp[tid] + zp[128 + tid];
}

// ---------------------------------------------------------------- pass 2
// CTA = (bh, 128-k tile). Warp owns 16 k-rows; w stays in registers.
// GEMM-A: (Khi+Klo) @ xhi (2-term, matches z). GEMM-B: w_hi @ x_hi.
__global__ __launch_bounds__(256) void hm_main(const float* __restrict__ K,
        const float* __restrict__ V, float* __restrict__ out) {
    extern __shared__ char sm[];
    const int tid = threadIdx.x, lane = tid & 31, wid = tid >> 5;
    const int k0 = blockIdx.x * 128, bh = blockIdx.y;
    uint32_t sb = s2u(sm);
    const uint32_t sx = ((uint32_t)lane & 7) << 4;
    const int q = lane & 3, r = lane >> 2;

    // K A-fragments in registers (4 kc x hi/lo x 4)
    uint32_t kfh[4][4], kfl[4][4];
    cpa_tile(sb + M_X(0, 0), g_K_hi + ((size_t)bh * KP + k0) * DD, tid);
    cpa_tile(sb + M_X(0, 1), g_K_lo + ((size_t)bh * KP + k0) * DD, tid);
    CPA_COMMIT();
    asm volatile("cp.async.wait_group 0;" ::: "memory");
    __syncthreads();
    {
        const uint32_t ar = (uint32_t)(wid * 16 + (lane & 15));
#pragma unroll
        for (int kc = 0; kc < 4; kc++) {
            const uint32_t acol = ((((uint32_t)lane >> 4) & 1) * 16 + kc * 32) ^ sx;
            ldsm4(kfh[kc], sb + M_X(0, 0) + ar * 128 + acol);
            ldsm4(kfl[kc], sb + M_X(0, 1) + ar * 128 + acol);
        }
    }
    __syncthreads();

    // x(0) + z(0)
    cpa_tile(sb + M_X(0, 0), g_xk_hi + (size_t)bh * NN * DD, tid);
    cpa_tile(sb + M_X(0, 1), g_xv_hi + (size_t)bh * NN * DD, tid);
    if (tid < 32) cpa(sb + M_RZ + tid * 16, g_z + (size_t)bh * NN + tid * 4);
    CPA_COMMIT();

    float accK[8][4], accV[8][4];
#pragma unroll
    for (int a = 0; a < 8; a++)
#pragma unroll
        for (int c = 0; c < 4; c++) { accK[a][c] = 0.f; accV[a][c] = 0.f; }
    float sloc0 = 0.f, sloc1 = 0.f;

    for (int it = 0; it < NN / 128; it++) {
        const int b = it & 1;
        if (it + 1 < NN / 128) {
            const size_t n1 = (size_t)bh * NN + (size_t)(it + 1) * 128;
            cpa_tile(sb + M_X(b ^ 1, 0), g_xk_hi + n1 * DD, tid);
            cpa_tile(sb + M_X(b ^ 1, 1), g_xv_hi + n1 * DD, tid);
            if (tid < 32) cpa(sb + M_RZ + (b ^ 1) * 512 + tid * 16, g_z + n1 + tid * 4);
        }
        CPA_COMMIT();
        cpa_wait1();
        __syncthreads();

        // ---- GEMM-A: C[16 j][4] = (Khi+Klo)[16k x 64d] @ xhi[128n x 64d]^T ----
        float C[16][4];
#pragma unroll
        for (int j = 0; j < 16; j++)
#pragma unroll
            for (int c = 0; c < 4; c++) C[j][c] = 0.f;
        {
            const uint32_t uXhi = sb + M_X(b, 0);
            const uint32_t br = (uint32_t)(((lane >> 4) & 1) * 8 + (lane & 7));
#pragma unroll
            for (int kc = 0; kc < 4; kc++) {
                const uint32_t bcol = ((((uint32_t)lane >> 3) & 1) * 16 + kc * 32) ^ sx;
                uint32_t bh2[8][4];
#pragma unroll
                for (int jj = 0; jj < 8; jj++)
                    ldsm4(bh2[jj], uXhi + (br + jj * 16) * 128 + bcol);
#pragma unroll
                for (int jj = 0; jj < 8; jj++) {
                    mma_f16(C[2 * jj],     kfh[kc], &bh2[jj][0]);
                    mma_f16(C[2 * jj + 1], kfh[kc], &bh2[jj][2]);
                }
#pragma unroll
                for (int jj = 0; jj < 8; jj++) {
                    mma_f16(C[2 * jj],     kfl[kc], &bh2[jj][0]);
                    mma_f16(C[2 * jj + 1], kfl[kc], &bh2[jj][2]);
                }
            }
        }

        // ---- epilogue in registers: w = exp(C)/z -> fp16 A-fragments ----
        uint32_t wh[8][4];
        {
            const float* zb = (const float*)(sm + M_RZ + b * 512);
#pragma unroll
            for (int nc = 0; nc < 8; nc++) {
                float2 z0 = *(const float2*)&zb[nc * 16 + 2 * q];
                float2 z1 = *(const float2*)&zb[nc * 16 + 8 + 2 * q];
                float r0 = __fdividef(1.f, z0.x), r1 = __fdividef(1.f, z0.y);
                float r2 = __fdividef(1.f, z1.x), r3 = __fdividef(1.f, z1.y);
                float w00 = __expf(C[2 * nc][0]) * r0,  w01 = __expf(C[2 * nc][1]) * r1;
                float w02 = __expf(C[2 * nc][2]) * r0,  w03 = __expf(C[2 * nc][3]) * r1;
                float w10 = __expf(C[2 * nc + 1][0]) * r2, w11 = __expf(C[2 * nc + 1][1]) * r3;
                float w12 = __expf(C[2 * nc + 1][2]) * r2, w13 = __expf(C[2 * nc + 1][3]) * r3;
                sloc0 += (w00 + w01) + (w10 + w11);
                sloc1 += (w02 + w03) + (w12 + w13);
                __half2 h;
                h = __floats2half2_rn(w00, w01); wh[nc][0] = *(uint32_t*)&h;
                h = __floats2half2_rn(w02, w03); wh[nc][1] = *(uint32_t*)&h;
                h = __floats2half2_rn(w10, w11); wh[nc][2] = *(uint32_t*)&h;
                h = __floats2half2_rn(w12, w13); wh[nc][3] = *(uint32_t*)&h;
            }
        }

        // ---- GEMM-B: accK += w @ xk_hi, accV += w @ xv_hi ----
        {
            const uint32_t xrow = (uint32_t)(((lane >> 3) & 1) * 8 + (lane & 7));
            const uint32_t hcb = (((uint32_t)lane >> 4) & 1) * 16;
#pragma unroll
            for (int nc = 0; nc < 8; nc++) {
                const uint32_t row = xrow + nc * 16;
#pragma unroll
                for (int dc = 0; dc < 4; dc++) {
                    const uint32_t col = ((uint32_t)dc * 32 + hcb) ^ sx;
                    uint32_t bkh[4], bvh[4];
                    ldsm4t(bkh, sb + M_X(b, 0) + row * 128 + col);
                    ldsm4t(bvh, sb + M_X(b, 1) + row * 128 + col);
#pragma unroll
                    for (int g = 0; g < 2; g++) {
                        const int jd = dc * 2 + g;
                        mma_f16(accK[jd], wh[nc], &bkh[g * 2]);
                        mma_f16(accV[jd], wh[nc], &bvh[g * 2]);
                    }
                }
            }
        }
        __syncthreads();   // x(b) consumed before next prefetch overwrites it
    }

    // ---- S reduction within quad (warp owns its 16 k-rows exclusively) ----
    sloc0 += __shfl_xor_sync(~0u, sloc0, 1);
    sloc0 += __shfl_xor_sync(~0u, sloc0, 2);
    sloc1 += __shfl_xor_sync(~0u, sloc1, 1);
    sloc1 += __shfl_xor_sync(~0u, sloc1, 2);
    const float rs0 = 1.0f / sloc0;
    const float rs1 = 1.0f / sloc1;

    // ---- finalize: gK = accK*rs - K, gV = accV*rs - V ----
    const int krow0 = k0 + wid * 16 + r;
#pragma unroll
    for (int jd = 0; jd < 8; jd++) {
        const int d = jd * 8 + 2 * q;
        size_t gi0 = ((size_t)bh * KP + krow0) * DD + d;
        size_t gi1 = ((size_t)bh * KP + krow0 + 8) * DD + d;
        float2 kv0 = *(const float2*)(K + gi0);
        float2 kv1 = *(const float2*)(K + gi1);
        float2 vv0 = *(const float2*)(V + gi0);
        float2 vv1 = *(const float2*)(V + gi1);
        float2 o;
        o.x = accK[jd][0] * rs0 - kv0.x; o.y = accK[jd][1] * rs0 - kv0.y;
        *(float2*)(out + gi0) = o;
        o.x = accK[jd][2] * rs1 - kv1.x; o.y = accK[jd][3] * rs1 - kv1.y;
        *(float2*)(out + gi1) = o;
        o.x = accV[jd][0] * rs0 - vv0.x; o.y = accV[jd][1] * rs0 - vv0.y;
        *(float2*)(out + (size_t)BH * KP * DD + gi0) = o;
        o.x = accV[jd][2] * rs1 - vv1.x; o.y = accV[jd][3] * rs1 - vv1.y;
        *(float2*)(out + (size_t)BH * KP * DD + gi1) = o;
    }
}

// ---------------------------------------------------------------- launch
extern "C" void kernel_launch(void* const* d_in, const int* in_sizes, int n_in,
                              void* d_out, int out_size) {
    (void)in_sizes; (void)n_in; (void)out_size;
    const float* K  = (const float*)d_in[0];
    const float* V  = (const float*)d_in[1];
    const float* xk = (const float*)d_in[2];
    const float* xv = (const float*)d_in[3];
    float* out = (float*)d_out;

    cudaFuncSetAttribute(hm_z,    cudaFuncAttributeMaxDynamicSharedMemorySize, Z_SMEM);
    cudaFuncSetAttribute(hm_main, cudaFuncAttributeMaxDynamicSharedMemorySize, M_SMEM);

    hm_split<<<dim3(BH * NN * DD / 4 / 256, 3), 256>>>(
        (const float4*)K, (const float4*)xk, (const float4*)xv);
    hm_z<<<dim3(NN / 128, BH), 256, Z_SMEM>>>();
    hm_main<<<dim3(KP / 128, BH), 256, M_SMEM>>>(K, V, out);
}

// round 15
// speedup vs baseline: 1.3921x; 1.3921x over previous
#include <cuda_runtime.h>
#include <cuda_fp16.h>
#include <stdint.h>

#define BH 64
#define KP 512
#define NN 4096
#define DD 64
#define XT 16384            // 128 x 64 fp16 tile, swizzled, 128B rows

// ---- hm_main smem layout (bytes): 3 x-arrays (xkhi, xklo, xvhi) x 2 buffers ----
#define M_X(b,c)  ((b) * 49152 + (c) * XT)
#define M_RZ  98304         // 2 x 512B raw z tiles
#define M_SMEM 99328

// ---- hm_z smem layout: xhi + K hi/lo double-buffered (2-term z) ----
#define Z_XHI 0
#define Z_K(b,c) (16384 + (b) * 32768 + (c) * XT)
#define Z_ZP 81920
#define Z_SMEM 82944

__device__ float g_z[BH * NN];
__device__ __align__(16) __half g_K_hi[BH * KP * DD];
__device__ __align__(16) __half g_K_lo[BH * KP * DD];
__device__ __align__(16) __half g_xk_hi[BH * NN * DD];
__device__ __align__(16) __half g_xk_lo[BH * NN * DD];
__device__ __align__(16) __half g_xv_hi[BH * NN * DD];

// ---------------------------------------------------------------- helpers
__device__ __forceinline__ uint32_t s2u(const void* p) {
    return (uint32_t)__cvta_generic_to_shared(p);
}
__device__ __forceinline__ void mma_f16(float* c, const uint32_t* a, const uint32_t* b) {
    asm volatile(
        "mma.sync.aligned.m16n8k16.row.col.f32.f16.f16.f32 "
        "{%0,%1,%2,%3}, {%4,%5,%6,%7}, {%8,%9}, {%0,%1,%2,%3};"
        : "+f"(c[0]), "+f"(c[1]), "+f"(c[2]), "+f"(c[3])
        : "r"(a[0]), "r"(a[1]), "r"(a[2]), "r"(a[3]), "r"(b[0]), "r"(b[1]));
}
__device__ __forceinline__ void ldsm4(uint32_t* r, uint32_t addr) {
    asm volatile("ldmatrix.sync.aligned.m8n8.x4.shared.b16 {%0,%1,%2,%3}, [%4];"
        : "=r"(r[0]), "=r"(r[1]), "=r"(r[2]), "=r"(r[3]) : "r"(addr));
}
__device__ __forceinline__ void ldsm4t(uint32_t* r, uint32_t addr) {
    asm volatile("ldmatrix.sync.aligned.m8n8.x4.trans.shared.b16 {%0,%1,%2,%3}, [%4];"
        : "=r"(r[0]), "=r"(r[1]), "=r"(r[2]), "=r"(r[3]) : "r"(addr));
}
__device__ __forceinline__ void cpa(uint32_t dst, const void* src) {
    asm volatile("cp.async.cg.shared.global [%0], [%1], 16;" :: "r"(dst), "l"(src));
}
#define CPA_COMMIT() asm volatile("cp.async.commit_group;" ::: "memory")
__device__ __forceinline__ void cpa_wait1() { asm volatile("cp.async.wait_group 1;" ::: "memory"); }

// 128x64 fp16 tile (16KB) global -> swizzled smem (128B rows). 256 thr.
__device__ __forceinline__ void cpa_tile(uint32_t sbase, const __half* g, int tid) {
#pragma unroll
    for (int j = 0; j < 4; j++) {
        int ch = tid + j * 256;
        int row = ch >> 3, c = ch & 7;
        uint32_t off = (uint32_t)row * 128 + (((uint32_t)c * 16) ^ (((uint32_t)row & 7) << 4));
        cpa(sbase + off, (const char*)g + (size_t)ch * 16);
    }
}

// ---------------------------------------------------------------- split
// which: 0=K (hi+lo), 1=xk (hi+lo), 2=xv (hi only)   [identical to R11]
__global__ __launch_bounds__(256) void hm_split(const float4* __restrict__ Ksrc,
        const float4* __restrict__ xksrc, const float4* __restrict__ xvsrc) {
    int which = blockIdx.y;
    int n4 = (which == 0) ? (BH * KP * DD / 4) : (BH * NN * DD / 4);
    int i = blockIdx.x * 256 + threadIdx.x;
    if (i >= n4) return;
    const float4* src = (which == 0) ? Ksrc : (which == 1) ? xksrc : xvsrc;
    float4 v = src[i];
    __half2 h0 = __floats2half2_rn(v.x, v.y);
    __half2 h1 = __floats2half2_rn(v.z, v.w);
    uint2 hw;
    hw.x = *(uint32_t*)&h0; hw.y = *(uint32_t*)&h1;
    if (which == 2) { ((uint2*)g_xv_hi)[i] = hw; return; }
    float2 f0 = __half22float2(h0), f1 = __half22float2(h1);
    __half2 l0 = __floats2half2_rn(v.x - f0.x, v.y - f0.y);
    __half2 l1 = __floats2half2_rn(v.z - f1.x, v.w - f1.y);
    uint2 lw;
    lw.x = *(uint32_t*)&l0; lw.y = *(uint32_t*)&l1;
    __half* hi = (which == 0) ? g_K_hi : g_xk_hi;
    __half* lo = (which == 0) ? g_K_lo : g_xk_lo;
    ((uint2*)hi)[i] = hw;
    ((uint2*)lo)[i] = lw;
}

// ---------------------------------------------------------------- pass 1: z
// dist_z = (Khi+Klo) @ xhi^T  (2-term). launch_bounds(256,2) pins 2 CTAs/SM.
__global__ __launch_bounds__(256, 2) void hm_z() {
    extern __shared__ char sm[];
    const int tid = threadIdx.x, lane = tid & 31, wid = tid >> 5;
    const int kw = wid >> 2, nw = wid & 3;
    const int n0 = blockIdx.x * 128, bh = blockIdx.y;
    uint32_t sb = s2u(sm);

    cpa_tile(sb + Z_XHI, g_xk_hi + ((size_t)bh * NN + n0) * DD, tid);
    cpa_tile(sb + Z_K(0, 0), g_K_hi + (size_t)bh * KP * DD, tid);
    cpa_tile(sb + Z_K(0, 1), g_K_lo + (size_t)bh * KP * DD, tid);
    CPA_COMMIT();

    float zl[8];
#pragma unroll
    for (int i = 0; i < 8; i++) zl[i] = 0.f;

    const uint32_t sx = ((uint32_t)lane & 7) << 4;
    const uint32_t ar = (uint32_t)(kw * 64 + (lane & 15));
    const uint32_t br = (uint32_t)(nw * 32 + ((lane >> 4) & 1) * 8 + (lane & 7));

    for (int kt = 0; kt < 4; kt++) {
        if (kt + 1 < 4) {
            cpa_tile(sb + Z_K((kt + 1) & 1, 0), g_K_hi + ((size_t)bh * KP + (kt + 1) * 128) * DD, tid);
            cpa_tile(sb + Z_K((kt + 1) & 1, 1), g_K_lo + ((size_t)bh * KP + (kt + 1) * 128) * DD, tid);
        }
        CPA_COMMIT();
        cpa_wait1();
        __syncthreads();

        float C[4][4][4];
#pragma unroll
        for (int a = 0; a < 4; a++)
#pragma unroll
            for (int b = 0; b < 4; b++)
#pragma unroll
                for (int c = 0; c < 4; c++) C[a][b][c] = 0.f;
        {
            const uint32_t uKhi = sb + Z_K(kt & 1, 0), uKlo = sb + Z_K(kt & 1, 1);
            const uint32_t uXhi = sb + Z_XHI;
#pragma unroll
            for (int kc = 0; kc < 4; kc++) {
                const uint32_t acol = ((((uint32_t)lane >> 4) & 1) * 16 + kc * 32) ^ sx;
                const uint32_t bcol = ((((uint32_t)lane >> 3) & 1) * 16 + kc * 32) ^ sx;
                uint32_t ah[4][4], al[4][4], bh2[2][4];
#pragma unroll
                for (int mb = 0; mb < 4; mb++) {
                    ldsm4(ah[mb], uKhi + (ar + mb * 16) * 128 + acol);
                    ldsm4(al[mb], uKlo + (ar + mb * 16) * 128 + acol);
                }
#pragma unroll
                for (int g = 0; g < 2; g++)
                    ldsm4(bh2[g], uXhi + (br + g * 16) * 128 + bcol);
#pragma unroll
                for (int mb = 0; mb < 4; mb++)
#pragma unroll
                    for (int g = 0; g < 2; g++)
#pragma unroll
                        for (int nbb = 0; nbb < 2; nbb++)
                            mma_f16(C[mb][g * 2 + nbb], ah[mb], &bh2[g][nbb * 2]);
#pragma unroll
                for (int mb = 0; mb < 4; mb++)
#pragma unroll
                    for (int g = 0; g < 2; g++)
#pragma unroll
                        for (int nbb = 0; nbb < 2; nbb++)
                            mma_f16(C[mb][g * 2 + nbb], al[mb], &bh2[g][nbb * 2]);
            }
        }
#pragma unroll
        for (int mb = 0; mb < 4; mb++)
#pragma unroll
            for (int j = 0; j < 4; j++) {
                zl[2 * j]     += __expf(C[mb][j][0]) + __expf(C[mb][j][2]);
                zl[2 * j + 1] += __expf(C[mb][j][1]) + __expf(C[mb][j][3]);
            }
        __syncthreads();
    }
#pragma unroll
    for (int i = 0; i < 8; i++) {
        zl[i] += __shfl_xor_sync(~0u, zl[i], 4);
        zl[i] += __shfl_xor_sync(~0u, zl[i], 8);
        zl[i] += __shfl_xor_sync(~0u, zl[i], 16);
    }
    float* zp = (float*)(sm + Z_ZP);
    if (lane < 4) {
#pragma unroll
        for (int j = 0; j < 4; j++)
            *(float2*)&zp[kw * 128 + nw * 32 + j * 8 + lane * 2] =
                make_float2(zl[2 * j], zl[2 * j + 1]);
    }
    __syncthreads();
    if (tid < 128)
        g_z[(size_t)bh * NN + n0 + tid] = zp[tid] + zp[128 + tid];
}

// ---------------------------------------------------------------- pass 2  [identical to R11]
// CTA = (bh, 128-k tile). Warp owns 16 k-rows; w stays in registers.
// GEMM-A: 3-term (Khi.xhi + Khi.xlo + Klo.xhi). GEMM-B: w_hi @ x_hi.
__global__ __launch_bounds__(256) void hm_main(const float* __restrict__ K,
        const float* __restrict__ V, float* __restrict__ out) {
    extern __shared__ char sm[];
    const int tid = threadIdx.x, lane = tid & 31, wid = tid >> 5;
    const int k0 = blockIdx.x * 128, bh = blockIdx.y;
    uint32_t sb = s2u(sm);
    const uint32_t sx = ((uint32_t)lane & 7) << 4;
    const int q = lane & 3, r = lane >> 2;

    // K A-fragments in registers (4 kc x hi/lo x 4)
    uint32_t kfh[4][4], kfl[4][4];
    cpa_tile(sb + M_X(0, 0), g_K_hi + ((size_t)bh * KP + k0) * DD, tid);
    cpa_tile(sb + M_X(0, 1), g_K_lo + ((size_t)bh * KP + k0) * DD, tid);
    CPA_COMMIT();
    asm volatile("cp.async.wait_group 0;" ::: "memory");
    __syncthreads();
    {
        const uint32_t ar = (uint32_t)(wid * 16 + (lane & 15));
#pragma unroll
        for (int kc = 0; kc < 4; kc++) {
            const uint32_t acol = ((((uint32_t)lane >> 4) & 1) * 16 + kc * 32) ^ sx;
            ldsm4(kfh[kc], sb + M_X(0, 0) + ar * 128 + acol);
            ldsm4(kfl[kc], sb + M_X(0, 1) + ar * 128 + acol);
        }
    }
    __syncthreads();

    // x(0) + z(0)
    cpa_tile(sb + M_X(0, 0), g_xk_hi + (size_t)bh * NN * DD, tid);
    cpa_tile(sb + M_X(0, 1), g_xk_lo + (size_t)bh * NN * DD, tid);
    cpa_tile(sb + M_X(0, 2), g_xv_hi + (size_t)bh * NN * DD, tid);
    if (tid < 32) cpa(sb + M_RZ + tid * 16, g_z + (size_t)bh * NN + tid * 4);
    CPA_COMMIT();

    float accK[8][4], accV[8][4];
#pragma unroll
    for (int a = 0; a < 8; a++)
#pragma unroll
        for (int c = 0; c < 4; c++) { accK[a][c] = 0.f; accV[a][c] = 0.f; }
    float sloc0 = 0.f, sloc1 = 0.f;

    for (int it = 0; it < NN / 128; it++) {
        const int b = it & 1;
        if (it + 1 < NN / 128) {
            const size_t n1 = (size_t)bh * NN + (size_t)(it + 1) * 128;
            cpa_tile(sb + M_X(b ^ 1, 0), g_xk_hi + n1 * DD, tid);
            cpa_tile(sb + M_X(b ^ 1, 1), g_xk_lo + n1 * DD, tid);
            cpa_tile(sb + M_X(b ^ 1, 2), g_xv_hi + n1 * DD, tid);
            if (tid < 32) cpa(sb + M_RZ + (b ^ 1) * 512 + tid * 16, g_z + n1 + tid * 4);
        }
        CPA_COMMIT();
        cpa_wait1();
        __syncthreads();

        // ---- GEMM-A: C[16 j][4] = K[16k x 64d] @ x[128n x 64d]^T, 3-term ----
        float C[16][4];
#pragma unroll
        for (int j = 0; j < 16; j++)
#pragma unroll
            for (int c = 0; c < 4; c++) C[j][c] = 0.f;
        {
            const uint32_t uXhi = sb + M_X(b, 0), uXlo = sb + M_X(b, 1);
            const uint32_t br = (uint32_t)(((lane >> 4) & 1) * 8 + (lane & 7));
#pragma unroll
            for (int kc = 0; kc < 4; kc++) {
                const uint32_t bcol = ((((uint32_t)lane >> 3) & 1) * 16 + kc * 32) ^ sx;
                uint32_t bh2[8][4], bl2[8][4];
#pragma unroll
                for (int jj = 0; jj < 8; jj++) {
                    ldsm4(bh2[jj], uXhi + (br + jj * 16) * 128 + bcol);
                    ldsm4(bl2[jj], uXlo + (br + jj * 16) * 128 + bcol);
                }
#pragma unroll
                for (int jj = 0; jj < 8; jj++) {
                    mma_f16(C[2 * jj],     kfh[kc], &bh2[jj][0]);
                    mma_f16(C[2 * jj + 1], kfh[kc], &bh2[jj][2]);
                }
#pragma unroll
                for (int jj = 0; jj < 8; jj++) {
                    mma_f16(C[2 * jj],     kfh[kc], &bl2[jj][0]);
                    mma_f16(C[2 * jj + 1], kfh[kc], &bl2[jj][2]);
                }
#pragma unroll
                for (int jj = 0; jj < 8; jj++) {
                    mma_f16(C[2 * jj],     kfl[kc], &bh2[jj][0]);
                    mma_f16(C[2 * jj + 1], kfl[kc], &bh2[jj][2]);
                }
            }
        }

        // ---- epilogue in registers: w = exp(C)/z -> fp16 A-fragments ----
        uint32_t wh[8][4];
        {
            const float* zb = (const float*)(sm + M_RZ + b * 512);
#pragma unroll
            for (int nc = 0; nc < 8; nc++) {
                float2 z0 = *(const float2*)&zb[nc * 16 + 2 * q];
                float2 z1 = *(const float2*)&zb[nc * 16 + 8 + 2 * q];
                float r0 = __fdividef(1.f, z0.x), r1 = __fdividef(1.f, z0.y);
                float r2 = __fdividef(1.f, z1.x), r3 = __fdividef(1.f, z1.y);
                float w00 = __expf(C[2 * nc][0]) * r0,  w01 = __expf(C[2 * nc][1]) * r1;
                float w02 = __expf(C[2 * nc][2]) * r0,  w03 = __expf(C[2 * nc][3]) * r1;
                float w10 = __expf(C[2 * nc + 1][0]) * r2, w11 = __expf(C[2 * nc + 1][1]) * r3;
                float w12 = __expf(C[2 * nc + 1][2]) * r2, w13 = __expf(C[2 * nc + 1][3]) * r3;
                sloc0 += (w00 + w01) + (w10 + w11);
                sloc1 += (w02 + w03) + (w12 + w13);
                __half2 h;
                h = __floats2half2_rn(w00, w01); wh[nc][0] = *(uint32_t*)&h;
                h = __floats2half2_rn(w02, w03); wh[nc][1] = *(uint32_t*)&h;
                h = __floats2half2_rn(w10, w11); wh[nc][2] = *(uint32_t*)&h;
                h = __floats2half2_rn(w12, w13); wh[nc][3] = *(uint32_t*)&h;
            }
        }

        // ---- GEMM-B: accK += w @ xk_hi, accV += w @ xv_hi ----
        {
            const uint32_t xrow = (uint32_t)(((lane >> 3) & 1) * 8 + (lane & 7));
            const uint32_t hcb = (((uint32_t)lane >> 4) & 1) * 16;
#pragma unroll
            for (int nc = 0; nc < 8; nc++) {
                const uint32_t row = xrow + nc * 16;
#pragma unroll
                for (int dc = 0; dc < 4; dc++) {
                    const uint32_t col = ((uint32_t)dc * 32 + hcb) ^ sx;
                    uint32_t bkh[4], bvh[4];
                    ldsm4t(bkh, sb + M_X(b, 0) + row * 128 + col);
                    ldsm4t(bvh, sb + M_X(b, 2) + row * 128 + col);
#pragma unroll
                    for (int g = 0; g < 2; g++) {
                        const int jd = dc * 2 + g;
                        mma_f16(accK[jd], wh[nc], &bkh[g * 2]);
                        mma_f16(accV[jd], wh[nc], &bvh[g * 2]);
                    }
                }
            }
        }
        __syncthreads();   // x(b) consumed before next prefetch overwrites it
    }

    // ---- S reduction within quad (warp owns its 16 k-rows exclusively) ----
    sloc0 += __shfl_xor_sync(~0u, sloc0, 1);
    sloc0 += __shfl_xor_sync(~0u, sloc0, 2);
    sloc1 += __shfl_xor_sync(~0u, sloc1, 1);
    sloc1 += __shfl_xor_sync(~0u, sloc1, 2);
    const float rs0 = 1.0f / sloc0;
    const float rs1 = 1.0f / sloc1;

    // ---- finalize: gK = accK*rs - K, gV = accV*rs - V ----
    const int krow0 = k0 + wid * 16 + r;
#pragma unroll
    for (int jd = 0; jd < 8; jd++) {
        const int d = jd * 8 + 2 * q;
        size_t gi0 = ((size_t)bh * KP + krow0) * DD + d;
        size_t gi1 = ((size_t)bh * KP + krow0 + 8) * DD + d;
        float2 kv0 = *(const float2*)(K + gi0);
        float2 kv1 = *(const float2*)(K + gi1);
        float2 vv0 = *(const float2*)(V + gi0);
        float2 vv1 = *(const float2*)(V + gi1);
        float2 o;
        o.x = accK[jd][0] * rs0 - kv0.x; o.y = accK[jd][1] * rs0 - kv0.y;
        *(float2*)(out + gi0) = o;
        o.x = accK[jd][2] * rs1 - kv1.x; o.y = accK[jd][3] * rs1 - kv1.y;
        *(float2*)(out + gi1) = o;
        o.x = accV[jd][0] * rs0 - vv0.x; o.y = accV[jd][1] * rs0 - vv0.y;
        *(float2*)(out + (size_t)BH * KP * DD + gi0) = o;
        o.x = accV[jd][2] * rs1 - vv1.x; o.y = accV[jd][3] * rs1 - vv1.y;
        *(float2*)(out + (size_t)BH * KP * DD + gi1) = o;
    }
}

// ---------------------------------------------------------------- launch
extern "C" void kernel_launch(void* const* d_in, const int* in_sizes, int n_in,
                              void* d_out, int out_size) {
    (void)in_sizes; (void)n_in; (void)out_size;
    const float* K  = (const float*)d_in[0];
    const float* V  = (const float*)d_in[1];
    const float* xk = (const float*)d_in[2];
    const float* xv = (const float*)d_in[3];
    float* out = (float*)d_out;

    cudaFuncSetAttribute(hm_z,    cudaFuncAttributeMaxDynamicSharedMemorySize, Z_SMEM);
    cudaFuncSetAttribute(hm_main, cudaFuncAttributeMaxDynamicSharedMemorySize, M_SMEM);

    hm_split<<<dim3(BH * NN * DD / 4 / 256, 3), 256>>>(
        (const float4*)K, (const float4*)xk, (const float4*)xv);
    hm_z<<<dim3(NN / 128, BH), 256, Z_SMEM>>>();
    hm_main<<<dim3(KP / 128, BH), 256, M_SMEM>>>(K, V, out);
}

// round 16
// speedup vs baseline: 1.4826x; 1.0650x over previous
#include <cuda_runtime.h>
#include <cuda_fp16.h>
#include <stdint.h>

#define BH 64
#define KP 512
#define NN 4096
#define DD 64
#define XT 16384            // 128 x 64 fp16 tile, swizzled, 128B rows

// ---- hm_main smem layout (bytes): 2 x-arrays (xkhi, xvhi) x 2 buffers ----
#define M_X(b,c)  ((b) * 32768 + (c) * XT)
#define M_RZ  65536         // 2 x 512B raw z tiles
#define M_SMEM 66560

// ---- hm_z smem layout: xhi + K hi/lo double-buffered (2-term z) ----
#define Z_XHI 0
#define Z_K(b,c) (16384 + (b) * 32768 + (c) * XT)
#define Z_ZP 81920
#define Z_SMEM 82944

__device__ float g_z[BH * NN];
__device__ __align__(16) __half g_K_hi[BH * KP * DD];
__device__ __align__(16) __half g_K_lo[BH * KP * DD];
__device__ __align__(16) __half g_xk_hi[BH * NN * DD];
__device__ __align__(16) __half g_xv_hi[BH * NN * DD];

// ---------------------------------------------------------------- helpers
__device__ __forceinline__ uint32_t s2u(const void* p) {
    return (uint32_t)__cvta_generic_to_shared(p);
}
__device__ __forceinline__ void mma_f16(float* c, const uint32_t* a, const uint32_t* b) {
    asm volatile(
        "mma.sync.aligned.m16n8k16.row.col.f32.f16.f16.f32 "
        "{%0,%1,%2,%3}, {%4,%5,%6,%7}, {%8,%9}, {%0,%1,%2,%3};"
        : "+f"(c[0]), "+f"(c[1]), "+f"(c[2]), "+f"(c[3])
        : "r"(a[0]), "r"(a[1]), "r"(a[2]), "r"(a[3]), "r"(b[0]), "r"(b[1]));
}
__device__ __forceinline__ void ldsm4(uint32_t* r, uint32_t addr) {
    asm volatile("ldmatrix.sync.aligned.m8n8.x4.shared.b16 {%0,%1,%2,%3}, [%4];"
        : "=r"(r[0]), "=r"(r[1]), "=r"(r[2]), "=r"(r[3]) : "r"(addr));
}
__device__ __forceinline__ void ldsm4t(uint32_t* r, uint32_t addr) {
    asm volatile("ldmatrix.sync.aligned.m8n8.x4.trans.shared.b16 {%0,%1,%2,%3}, [%4];"
        : "=r"(r[0]), "=r"(r[1]), "=r"(r[2]), "=r"(r[3]) : "r"(addr));
}
__device__ __forceinline__ void cpa(uint32_t dst, const void* src) {
    asm volatile("cp.async.cg.shared.global [%0], [%1], 16;" :: "r"(dst), "l"(src));
}
#define CPA_COMMIT() asm volatile("cp.async.commit_group;" ::: "memory")
__device__ __forceinline__ void cpa_wait1() { asm volatile("cp.async.wait_group 1;" ::: "memory"); }

// 128x64 fp16 tile (16KB) global -> swizzled smem (128B rows). 256 thr.
__device__ __forceinline__ void cpa_tile(uint32_t sbase, const __half* g, int tid) {
#pragma unroll
    for (int j = 0; j < 4; j++) {
        int ch = tid + j * 256;
        int row = ch >> 3, c = ch & 7;
        uint32_t off = (uint32_t)row * 128 + (((uint32_t)c * 16) ^ (((uint32_t)row & 7) << 4));
        cpa(sbase + off, (const char*)g + (size_t)ch * 16);
    }
}

// ---------------------------------------------------------------- split
// which: 0=K (hi+lo), 1=xk (hi only), 2=xv (hi only)
__global__ __launch_bounds__(256) void hm_split(const float4* __restrict__ Ksrc,
        const float4* __restrict__ xksrc, const float4* __restrict__ xvsrc) {
    int which = blockIdx.y;
    int n4 = (which == 0) ? (BH * KP * DD / 4) : (BH * NN * DD / 4);
    int i = blockIdx.x * 256 + threadIdx.x;
    if (i >= n4) return;
    const float4* src = (which == 0) ? Ksrc : (which == 1) ? xksrc : xvsrc;
    float4 v = src[i];
    __half2 h0 = __floats2half2_rn(v.x, v.y);
    __half2 h1 = __floats2half2_rn(v.z, v.w);
    uint2 hw;
    hw.x = *(uint32_t*)&h0; hw.y = *(uint32_t*)&h1;
    if (which == 1) { ((uint2*)g_xk_hi)[i] = hw; return; }
    if (which == 2) { ((uint2*)g_xv_hi)[i] = hw; return; }
    float2 f0 = __half22float2(h0), f1 = __half22float2(h1);
    __half2 l0 = __floats2half2_rn(v.x - f0.x, v.y - f0.y);
    __half2 l1 = __floats2half2_rn(v.z - f1.x, v.w - f1.y);
    uint2 lw;
    lw.x = *(uint32_t*)&l0; lw.y = *(uint32_t*)&l1;
    ((uint2*)g_K_hi)[i] = hw;
    ((uint2*)g_K_lo)[i] = lw;
}

// ---------------------------------------------------------------- pass 1: z
// dist_z = (Khi+Klo) @ xhi^T  (2-term). launch_bounds(256,2) pins 2 CTAs/SM.
// [identical to R15]
__global__ __launch_bounds__(256, 2) void hm_z() {
    extern __shared__ char sm[];
    const int tid = threadIdx.x, lane = tid & 31, wid = tid >> 5;
    const int kw = wid >> 2, nw = wid & 3;
    const int n0 = blockIdx.x * 128, bh = blockIdx.y;
    uint32_t sb = s2u(sm);

    cpa_tile(sb + Z_XHI, g_xk_hi + ((size_t)bh * NN + n0) * DD, tid);
    cpa_tile(sb + Z_K(0, 0), g_K_hi + (size_t)bh * KP * DD, tid);
    cpa_tile(sb + Z_K(0, 1), g_K_lo + (size_t)bh * KP * DD, tid);
    CPA_COMMIT();

    float zl[8];
#pragma unroll
    for (int i = 0; i < 8; i++) zl[i] = 0.f;

    const uint32_t sx = ((uint32_t)lane & 7) << 4;
    const uint32_t ar = (uint32_t)(kw * 64 + (lane & 15));
    const uint32_t br = (uint32_t)(nw * 32 + ((lane >> 4) & 1) * 8 + (lane & 7));

    for (int kt = 0; kt < 4; kt++) {
        if (kt + 1 < 4) {
            cpa_tile(sb + Z_K((kt + 1) & 1, 0), g_K_hi + ((size_t)bh * KP + (kt + 1) * 128) * DD, tid);
            cpa_tile(sb + Z_K((kt + 1) & 1, 1), g_K_lo + ((size_t)bh * KP + (kt + 1) * 128) * DD, tid);
        }
        CPA_COMMIT();
        cpa_wait1();
        __syncthreads();

        float C[4][4][4];
#pragma unroll
        for (int a = 0; a < 4; a++)
#pragma unroll
            for (int b = 0; b < 4; b++)
#pragma unroll
                for (int c = 0; c < 4; c++) C[a][b][c] = 0.f;
        {
            const uint32_t uKhi = sb + Z_K(kt & 1, 0), uKlo = sb + Z_K(kt & 1, 1);
            const uint32_t uXhi = sb + Z_XHI;
#pragma unroll
            for (int kc = 0; kc < 4; kc++) {
                const uint32_t acol = ((((uint32_t)lane >> 4) & 1) * 16 + kc * 32) ^ sx;
                const uint32_t bcol = ((((uint32_t)lane >> 3) & 1) * 16 + kc * 32) ^ sx;
                uint32_t ah[4][4], al[4][4], bh2[2][4];
#pragma unroll
                for (int mb = 0; mb < 4; mb++) {
                    ldsm4(ah[mb], uKhi + (ar + mb * 16) * 128 + acol);
                    ldsm4(al[mb], uKlo + (ar + mb * 16) * 128 + acol);
                }
#pragma unroll
                for (int g = 0; g < 2; g++)
                    ldsm4(bh2[g], uXhi + (br + g * 16) * 128 + bcol);
#pragma unroll
                for (int mb = 0; mb < 4; mb++)
#pragma unroll
                    for (int g = 0; g < 2; g++)
#pragma unroll
                        for (int nbb = 0; nbb < 2; nbb++)
                            mma_f16(C[mb][g * 2 + nbb], ah[mb], &bh2[g][nbb * 2]);
#pragma unroll
                for (int mb = 0; mb < 4; mb++)
#pragma unroll
                    for (int g = 0; g < 2; g++)
#pragma unroll
                        for (int nbb = 0; nbb < 2; nbb++)
                            mma_f16(C[mb][g * 2 + nbb], al[mb], &bh2[g][nbb * 2]);
            }
        }
#pragma unroll
        for (int mb = 0; mb < 4; mb++)
#pragma unroll
            for (int j = 0; j < 4; j++) {
                zl[2 * j]     += __expf(C[mb][j][0]) + __expf(C[mb][j][2]);
                zl[2 * j + 1] += __expf(C[mb][j][1]) + __expf(C[mb][j][3]);
            }
        __syncthreads();
    }
#pragma unroll
    for (int i = 0; i < 8; i++) {
        zl[i] += __shfl_xor_sync(~0u, zl[i], 4);
        zl[i] += __shfl_xor_sync(~0u, zl[i], 8);
        zl[i] += __shfl_xor_sync(~0u, zl[i], 16);
    }
    float* zp = (float*)(sm + Z_ZP);
    if (lane < 4) {
#pragma unroll
        for (int j = 0; j < 4; j++)
            *(float2*)&zp[kw * 128 + nw * 32 + j * 8 + lane * 2] =
                make_float2(zl[2 * j], zl[2 * j + 1]);
    }
    __syncthreads();
    if (tid < 128)
        g_z[(size_t)bh * NN + n0 + tid] = zp[tid] + zp[128 + tid];
}

// ---------------------------------------------------------------- pass 2
// CTA = (bh, 128-k tile). Warp owns 16 k-rows; w stays in registers.
// GEMM-A: 2-term (Khi+Klo) @ xhi — IDENTICAL logits to z pass. GEMM-B: w @ x_hi.
__global__ __launch_bounds__(256) void hm_main(const float* __restrict__ K,
        const float* __restrict__ V, float* __restrict__ out) {
    extern __shared__ char sm[];
    const int tid = threadIdx.x, lane = tid & 31, wid = tid >> 5;
    const int k0 = blockIdx.x * 128, bh = blockIdx.y;
    uint32_t sb = s2u(sm);
    const uint32_t sx = ((uint32_t)lane & 7) << 4;
    const int q = lane & 3, r = lane >> 2;

    // K A-fragments in registers (4 kc x hi/lo x 4)
    uint32_t kfh[4][4], kfl[4][4];
    cpa_tile(sb + M_X(0, 0), g_K_hi + ((size_t)bh * KP + k0) * DD, tid);
    cpa_tile(sb + M_X(0, 1), g_K_lo + ((size_t)bh * KP + k0) * DD, tid);
    CPA_COMMIT();
    asm volatile("cp.async.wait_group 0;" ::: "memory");
    __syncthreads();
    {
        const uint32_t ar = (uint32_t)(wid * 16 + (lane & 15));
#pragma unroll
        for (int kc = 0; kc < 4; kc++) {
            const uint32_t acol = ((((uint32_t)lane >> 4) & 1) * 16 + kc * 32) ^ sx;
            ldsm4(kfh[kc], sb + M_X(0, 0) + ar * 128 + acol);
            ldsm4(kfl[kc], sb + M_X(0, 1) + ar * 128 + acol);
        }
    }
    __syncthreads();

    // x(0) + z(0)
    cpa_tile(sb + M_X(0, 0), g_xk_hi + (size_t)bh * NN * DD, tid);
    cpa_tile(sb + M_X(0, 1), g_xv_hi + (size_t)bh * NN * DD, tid);
    if (tid < 32) cpa(sb + M_RZ + tid * 16, g_z + (size_t)bh * NN + tid * 4);
    CPA_COMMIT();

    float accK[8][4], accV[8][4];
#pragma unroll
    for (int a = 0; a < 8; a++)
#pragma unroll
        for (int c = 0; c < 4; c++) { accK[a][c] = 0.f; accV[a][c] = 0.f; }
    float sloc0 = 0.f, sloc1 = 0.f;

    for (int it = 0; it < NN / 128; it++) {
        const int b = it & 1;
        if (it + 1 < NN / 128) {
            const size_t n1 = (size_t)bh * NN + (size_t)(it + 1) * 128;
            cpa_tile(sb + M_X(b ^ 1, 0), g_xk_hi + n1 * DD, tid);
            cpa_tile(sb + M_X(b ^ 1, 1), g_xv_hi + n1 * DD, tid);
            if (tid < 32) cpa(sb + M_RZ + (b ^ 1) * 512 + tid * 16, g_z + n1 + tid * 4);
        }
        CPA_COMMIT();
        cpa_wait1();
        __syncthreads();

        // ---- GEMM-A: C[16 j][4] = (Khi+Klo)[16k x 64d] @ xhi[128n x 64d]^T ----
        float C[16][4];
#pragma unroll
        for (int j = 0; j < 16; j++)
#pragma unroll
            for (int c = 0; c < 4; c++) C[j][c] = 0.f;
        {
            const uint32_t uXhi = sb + M_X(b, 0);
            const uint32_t br = (uint32_t)(((lane >> 4) & 1) * 8 + (lane & 7));
#pragma unroll
            for (int kc = 0; kc < 4; kc++) {
                const uint32_t bcol = ((((uint32_t)lane >> 3) & 1) * 16 + kc * 32) ^ sx;
                uint32_t bh2[8][4];
#pragma unroll
                for (int jj = 0; jj < 8; jj++)
                    ldsm4(bh2[jj], uXhi + (br + jj * 16) * 128 + bcol);
#pragma unroll
                for (int jj = 0; jj < 8; jj++) {
                    mma_f16(C[2 * jj],     kfh[kc], &bh2[jj][0]);
                    mma_f16(C[2 * jj + 1], kfh[kc], &bh2[jj][2]);
                }
#pragma unroll
                for (int jj = 0; jj < 8; jj++) {
                    mma_f16(C[2 * jj],     kfl[kc], &bh2[jj][0]);
                    mma_f16(C[2 * jj + 1], kfl[kc], &bh2[jj][2]);
                }
            }
        }

        // ---- epilogue in registers: w = exp(C)/z -> fp16 A-fragments ----
        uint32_t wh[8][4];
        {
            const float* zb = (const float*)(sm + M_RZ + b * 512);
#pragma unroll
            for (int nc = 0; nc < 8; nc++) {
                float2 z0 = *(const float2*)&zb[nc * 16 + 2 * q];
                float2 z1 = *(const float2*)&zb[nc * 16 + 8 + 2 * q];
                float r0 = __fdividef(1.f, z0.x), r1 = __fdividef(1.f, z0.y);
                float r2 = __fdividef(1.f, z1.x), r3 = __fdividef(1.f, z1.y);
                float w00 = __expf(C[2 * nc][0]) * r0,  w01 = __expf(C[2 * nc][1]) * r1;
                float w02 = __expf(C[2 * nc][2]) * r0,  w03 = __expf(C[2 * nc][3]) * r1;
                float w10 = __expf(C[2 * nc + 1][0]) * r2, w11 = __expf(C[2 * nc + 1][1]) * r3;
                float w12 = __expf(C[2 * nc + 1][2]) * r2, w13 = __expf(C[2 * nc + 1][3]) * r3;
                sloc0 += (w00 + w01) + (w10 + w11);
                sloc1 += (w02 + w03) + (w12 + w13);
                __half2 h;
                h = __floats2half2_rn(w00, w01); wh[nc][0] = *(uint32_t*)&h;
                h = __floats2half2_rn(w02, w03); wh[nc][1] = *(uint32_t*)&h;
                h = __floats2half2_rn(w10, w11); wh[nc][2] = *(uint32_t*)&h;
                h = __floats2half2_rn(w12, w13); wh[nc][3] = *(uint32_t*)&h;
            }
        }

        // ---- GEMM-B: accK += w @ xk_hi, accV += w @ xv_hi ----
        {
            const uint32_t xrow = (uint32_t)(((lane >> 3) & 1) * 8 + (lane & 7));
            const uint32_t hcb = (((uint32_t)lane >> 4) & 1) * 16;
#pragma unroll
            for (int nc = 0; nc < 8; nc++) {
                const uint32_t row = xrow + nc * 16;
#pragma unroll
                for (int dc = 0; dc < 4; dc++) {
                    const uint32_t col = ((uint32_t)dc * 32 + hcb) ^ sx;
                    uint32_t bkh[4], bvh[4];
                    ldsm4t(bkh, sb + M_X(b, 0) + row * 128 + col);
                    ldsm4t(bvh, sb + M_X(b, 1) + row * 128 + col);
#pragma unroll
                    for (int g = 0; g < 2; g++) {
                        const int jd = dc * 2 + g;
                        mma_f16(accK[jd], wh[nc], &bkh[g * 2]);
                        mma_f16(accV[jd], wh[nc], &bvh[g * 2]);
                    }
                }
            }
        }
        __syncthreads();   // x(b) consumed before next prefetch overwrites it
    }

    // ---- S reduction within quad (warp owns its 16 k-rows exclusively) ----
    sloc0 += __shfl_xor_sync(~0u, sloc0, 1);
    sloc0 += __shfl_xor_sync(~0u, sloc0, 2);
    sloc1 += __shfl_xor_sync(~0u, sloc1, 1);
    sloc1 += __shfl_xor_sync(~0u, sloc1, 2);
    const float rs0 = 1.0f / sloc0;
    const float rs1 = 1.0f / sloc1;

    // ---- finalize: gK = accK*rs - K, gV = accV*rs - V ----
    const int krow0 = k0 + wid * 16 + r;
#pragma unroll
    for (int jd = 0; jd < 8; jd++) {
        const int d = jd * 8 + 2 * q;
        size_t gi0 = ((size_t)bh * KP + krow0) * DD + d;
        size_t gi1 = ((size_t)bh * KP + krow0 + 8) * DD + d;
        float2 kv0 = *(const float2*)(K + gi0);
        float2 kv1 = *(const float2*)(K + gi1);
        float2 vv0 = *(const float2*)(V + gi0);
        float2 vv1 = *(const float2*)(V + gi1);
        float2 o;
        o.x = accK[jd][0] * rs0 - kv0.x; o.y = accK[jd][1] * rs0 - kv0.y;
        *(float2*)(out + gi0) = o;
        o.x = accK[jd][2] * rs1 - kv1.x; o.y = accK[jd][3] * rs1 - kv1.y;
        *(float2*)(out + gi1) = o;
        o.x = accV[jd][0] * rs0 - vv0.x; o.y = accV[jd][1] * rs0 - vv0.y;
        *(float2*)(out + (size_t)BH * KP * DD + gi0) = o;
        o.x = accV[jd][2] * rs1 - vv1.x; o.y = accV[jd][3] * rs1 - vv1.y;
        *(float2*)(out + (size_t)BH * KP * DD + gi1) = o;
    }
}

// ---------------------------------------------------------------- launch
extern "C" void kernel_launch(void* const* d_in, const int* in_sizes, int n_in,
                              void* d_out, int out_size) {
    (void)in_sizes; (void)n_in; (void)out_size;
    const float* K  = (const float*)d_in[0];
    const float* V  = (const float*)d_in[1];
    const float* xk = (const float*)d_in[2];
    const float* xv = (const float*)d_in[3];
    float* out = (float*)d_out;

    cudaFuncSetAttribute(hm_z,    cudaFuncAttributeMaxDynamicSharedMemorySize, Z_SMEM);
    cudaFuncSetAttribute(hm_main, cudaFuncAttributeMaxDynamicSharedMemorySize, M_SMEM);

    hm_split<<<dim3(BH * NN * DD / 4 / 256, 3), 256>>>(
        (const float4*)K, (const float4*)xk, (const float4*)xv);
    hm_z<<<dim3(NN / 128, BH), 256, Z_SMEM>>>();
    hm_main<<<dim3(KP / 128, BH), 256, M_SMEM>>>(K, V, out);
}